// round 16
// baseline (speedup 1.0000x reference)
#include <cuda_runtime.h>
#include <cuda_bf16.h>
#include <cuda_fp16.h>
#include <cstdint>

// Problem constants
#define V_  20000
#define M_  32
#define E_  128
#define H_  4
#define N_  8192
#define L_  64
#define C_  128
#define WPB 2          // words per block in word_embed kernel

// conv doc tile geometry (fp16 pairs): DS2 u32 per row (64 data + 4 pad)
#define DS2 68
#define DOCROWS 68             // 64 + 4 pad rows (pads only feed discarded t)
#define DOCN2  (DOCROWS * DS2)

// ---------------- device scratch (no allocations allowed) ----------------
__device__ float g_word_embeds[V_ * E_];          // [V,E]
__device__ float g_fcT[3 * C_ * E_];              // [i][c] = fc_w[c][i]
// transposed scalar weight copies (LDG.32 coalesced; dup happens in-register)
__device__ float g_wqT[E_ * E_];                  // [e*128+i] = Wq[i][e]
__device__ float g_wkR[E_ * E_];                  // [r*128+i] = Wk[r][i] (row-major)
__device__ float g_wvT[E_ * E_];                  // [e*128+i] = Wv[i][e]
__device__ float g_woT[E_ * E_];                  // [e*128+i] = out_w[i][e]
// fragment-packed fp16 conv weights (+256 pad uint4 for unguarded prefetch)
__device__ uint4 g_wmma[24576 + 256];
#define WOFF3 0
#define WOFF4 6144     // 3*8*1024/4
#define WOFF5 14336    // 6144 + 4*8*1024/4

typedef unsigned long long ull;

// ---------------- f32x2 helpers ----------------
__device__ __forceinline__ ull pk2(float x, float y) {
    ull r;
    asm("mov.b64 %0, {%1,%2};" : "=l"(r) : "f"(x), "f"(y));
    return r;
}
__device__ __forceinline__ void unpk(ull v, float& x, float& y) {
    asm("mov.b64 {%0,%1}, %2;" : "=f"(x), "=f"(y) : "l"(v));
}
__device__ __forceinline__ ull ffma2(ull a, ull b, ull c) {
    ull d;
    asm("fma.rn.f32x2 %0, %1, %2, %3;" : "=l"(d) : "l"(a), "l"(b), "l"(c));
    return d;
}
__device__ __forceinline__ ull add2(ull a, ull b) {
    ull d;
    asm("add.rn.f32x2 %0, %1, %2;" : "=l"(d) : "l"(a), "l"(b));
    return d;
}

// fp16 m16n8k16 MMA, fp32 accumulate
__device__ __forceinline__ void mma_f16(float* d,
                                        uint32_t a0, uint32_t a1, uint32_t a2, uint32_t a3,
                                        uint32_t b0, uint32_t b1) {
    asm volatile(
        "mma.sync.aligned.m16n8k16.row.col.f32.f16.f16.f32 "
        "{%0,%1,%2,%3}, {%4,%5,%6,%7}, {%8,%9}, {%0,%1,%2,%3};"
        : "+f"(d[0]), "+f"(d[1]), "+f"(d[2]), "+f"(d[3])
        : "r"(a0), "r"(a1), "r"(a2), "r"(a3), "r"(b0), "r"(b1));
}

// ---------------- prep kernels (three launches: word lands at ncu index 3) --
#define PSEG3 (3 * C_ * E_)
#define PW3   (3 * 8 * 1024)
#define PW4   (4 * 8 * 1024)
#define PW5   (5 * 8 * 1024)
#define PREPW_TOTAL (PW3 + PW4 + PW5)
#define PREPT_TOTAL (4 * E_ * E_)

__global__ void prep_t_kernel(const float* __restrict__ in_w,
                              const float* __restrict__ out_w) {
    int idx = blockIdx.x * blockDim.x + threadIdx.x;
    if (idx >= PREPT_TOTAL) return;
    int seg = idx >> 14;          // 16384 per segment
    int r   = idx & 16383;
    int a = r >> 7, i = r & 127;
    if (seg == 0)      g_wqT[r] = in_w[i * E_ + a];
    else if (seg == 1) g_wkR[r] = in_w[(E_ + a) * E_ + i];
    else if (seg == 2) g_wvT[r] = in_w[(2 * E_ + i) * E_ + a];
    else               g_woT[r] = out_w[i * E_ + a];
}

__global__ void prep_fc_kernel(const float* __restrict__ fc_w) {
    int idx = blockIdx.x * blockDim.x + threadIdx.x;
    if (idx >= PSEG3) return;
    int i = idx >> 7, c = idx & 127;
    g_fcT[idx] = fc_w[c * (3 * C_) + i];
}

// fp16 k16 fragment pack (unchanged from R15)
__device__ __forceinline__ void prep_wmma_one(const float* __restrict__ w, int K,
                                              int dst_off_u4, int idx) {
    int s    = idx >> 10;
    int rem  = idx & 1023;
    int p    = rem >> 7;
    int lane = (rem >> 2) & 31;
    int q    = rem & 3;
    int j   = s >> 3, ec8 = s & 7;
    int nt  = 2 * p + (q >> 1);
    int klo = 2 * (lane & 3) + 8 * (q & 1);
    int c   = nt * 8 + (lane >> 2);
    int e   = ec8 * 16 + klo;
    __half2 h = __floats2half2_rn(w[(c * E_ + e) * K + j],
                                  w[(c * E_ + e + 1) * K + j]);
    reinterpret_cast<uint32_t*>(g_wmma)[dst_off_u4 * 4 + idx] =
        *reinterpret_cast<uint32_t*>(&h);
}

__global__ void prep_w_kernel(const float* __restrict__ w3,
                              const float* __restrict__ w4,
                              const float* __restrict__ w5) {
    int idx = blockIdx.x * blockDim.x + threadIdx.x;
    if (idx >= PREPW_TOTAL) return;
    if (idx < PW3) { prep_wmma_one(w3, 3, WOFF3, idx); return; }
    idx -= PW3;
    if (idx < PW4) { prep_wmma_one(w4, 4, WOFF4, idx); return; }
    idx -= PW4;
    prep_wmma_one(w5, 5, WOFF5, idx);
}

// ---------------- word embedding kernel: 2 words per block, f32x2-packed ----
// Weights streamed as scalar LDG.32 (coalesced, 1 wf) and dup'd in-register.
struct WSmem {
    float2 ctx2[M_][129];
    float2 u[900];
    int idx[WPB][M_];
    int len[WPB];
};
#define U_Q2   0
#define U_QH2  128
#define U_G2   256
#define U_ATT  768
#define U_O2   0
#define U_CB   896

__global__ __launch_bounds__(128) void word_embed_kernel(
    const int* __restrict__ word2news, const int* __restrict__ word2news_len,
    const float* __restrict__ table,
    const float* __restrict__ in_b, const float* __restrict__ out_b)
{
    extern __shared__ char smem_raw[];
    WSmem& s = *reinterpret_cast<WSmem*>(smem_raw);

    const int v0 = blockIdx.x * WPB;
    const int tid = threadIdx.x;
    const int lane = tid & 31, warp = tid >> 5;

    if (tid < WPB * M_) {
        int w = tid >> 5, m = tid & 31;
        s.idx[w][m] = word2news[(v0 + w) * M_ + m];
    }
    if (tid < WPB) s.len[tid] = word2news_len[v0 + tid];
    __syncthreads();

    const int len0 = s.len[0], len1 = s.len[1];

    // gather ctx rows: warp handles row m = m4*4 + warp; stride-32 column
    // assignment so STS.64 is only 2-way conflicted (vs 8-way for 4-consecutive)
    #pragma unroll
    for (int m4 = 0; m4 < 8; ++m4) {
        int m = m4 * 4 + warp;
        const float* r0 = &table[s.idx[0][m] * E_];
        const float* r1 = &table[s.idx[1][m] * E_];
        #pragma unroll
        for (int k = 0; k < 4; ++k) {
            int col = lane + 32 * k;
            s.ctx2[m][col] = make_float2(r0[col], r1[col]);
        }
    }
    __syncthreads();

    // masked mean query (scalar masks differ per word)
    {
        float inv0 = 1.0f / (float)(len0 > 0 ? len0 : 1);
        float inv1 = 1.0f / (float)(len1 > 0 ? len1 : 1);
        float a0 = 0.0f, a1 = 0.0f;
        #pragma unroll
        for (int m = 0; m < M_; ++m) {
            float2 v = s.ctx2[m][tid];
            if (m < len0) a0 += v.x;
            if (m < len1) a1 += v.y;
        }
        s.u[U_Q2 + tid] = make_float2(a0 * inv0, a1 * inv1);
    }
    __syncthreads();

    // qh = q @ Wq^T + bq     (scalar LDG.32 weights, register-dup, FFMA2)
    {
        ull aa = 0, ab = 0;
        #pragma unroll 8
        for (int e = 0; e < E_; e += 2) {
            float wa = g_wqT[e * E_ + tid];
            float wb = g_wqT[(e + 1) * E_ + tid];
            aa = ffma2(*(const ull*)&s.u[U_Q2 + e],     pk2(wa, wa), aa);
            ab = ffma2(*(const ull*)&s.u[U_Q2 + e + 1], pk2(wb, wb), ab);
        }
        float bq = in_b[tid];
        *(ull*)&s.u[U_QH2 + tid] = add2(add2(aa, ab), pk2(bq, bq));
    }
    __syncthreads();

    // g2[h][e] = sum_d qh[h*32+d] * Wk[h*32+d][e]
    {
        #pragma unroll
        for (int h = 0; h < H_; ++h) {
            ull aa = 0, ab = 0;
            #pragma unroll 8
            for (int d = 0; d < 32; d += 2) {
                float wa = g_wkR[(h * 32 + d) * E_ + tid];
                float wb = g_wkR[(h * 32 + d + 1) * E_ + tid];
                aa = ffma2(*(const ull*)&s.u[U_QH2 + h * 32 + d],     pk2(wa, wa), aa);
                ab = ffma2(*(const ull*)&s.u[U_QH2 + h * 32 + d + 1], pk2(wb, wb), ab);
            }
            *(ull*)&s.u[U_G2 + h * 128 + tid] = add2(aa, ab);
        }
    }
    if (tid < WPB * H_) {
        int w = tid >> 2, h = tid & 3;
        float c = 0.0f;
        #pragma unroll 8
        for (int d = 0; d < 32; ++d) {
            float2 q2v = s.u[U_QH2 + h * 32 + d];
            c += (w == 0 ? q2v.x : q2v.y) * in_b[E_ + h * 32 + d];
        }
        ((float*)(s.u + U_CB))[h * 2 + w] = c;
    }
    __syncthreads();

    // scores + per-head softmax: thread = (h = warp, m = lane); both words packed
    {
        const int h = warp, m = lane;
        ull sa = 0, sb = 0;
        #pragma unroll 8
        for (int e = 0; e < E_; e += 2) {
            sa = ffma2(*(const ull*)&s.ctx2[m][e],
                       *(const ull*)&s.u[U_G2 + h * 128 + e], sa);
            sb = ffma2(*(const ull*)&s.ctx2[m][e + 1],
                       *(const ull*)&s.u[U_G2 + h * 128 + e + 1], sb);
        }
        float s0, s1;
        unpk(add2(sa, sb), s0, s1);
        float2 cb = s.u[U_CB + h];
        s0 = (s0 + cb.x) * 0.17677669529663688f;
        s1 = (s1 + cb.y) * 0.17677669529663688f;
        if (m >= len0) s0 = -1e30f;
        if (m >= len1) s1 = -1e30f;
        float w0 = s0, w1 = s1;
        #pragma unroll
        for (int o = 16; o; o >>= 1) {
            w0 = fmaxf(w0, __shfl_xor_sync(0xFFFFFFFFu, w0, o));
            w1 = fmaxf(w1, __shfl_xor_sync(0xFFFFFFFFu, w1, o));
        }
        float p0 = __expf(s0 - w0), p1 = __expf(s1 - w1);
        float ps0 = p0, ps1 = p1;
        #pragma unroll
        for (int o = 16; o; o >>= 1) {
            ps0 += __shfl_xor_sync(0xFFFFFFFFu, ps0, o);
            ps1 += __shfl_xor_sync(0xFFFFFFFFu, ps1, o);
        }
        *(ull*)&s.u[U_ATT + h * 32 + m] = pk2(p0 / ps0, p1 / ps1);
    }
    __syncthreads();

    // ch2[h][e] = sum_m attn[h,m] * ctx[m,e]   (overwrites g2 region)
    {
        #pragma unroll
        for (int h = 0; h < H_; ++h) {
            ull aa = 0, ab = 0;
            #pragma unroll 8
            for (int m = 0; m < M_; m += 2) {
                aa = ffma2(*(const ull*)&s.u[U_ATT + h * 32 + m],
                           *(const ull*)&s.ctx2[m][tid], aa);
                ab = ffma2(*(const ull*)&s.u[U_ATT + h * 32 + m + 1],
                           *(const ull*)&s.ctx2[m + 1][tid], ab);
            }
            *(ull*)&s.u[U_G2 + h * 128 + tid] = add2(aa, ab);
        }
    }
    __syncthreads();

    // o[i] = ch[h(i)] . Wv[i] + bv[i]    (o2 aliases q2)
    {
        const int h = warp;
        ull aa = 0, ab = 0;
        #pragma unroll 8
        for (int e = 0; e < E_; e += 2) {
            float wa = g_wvT[e * E_ + tid];
            float wb = g_wvT[(e + 1) * E_ + tid];
            aa = ffma2(*(const ull*)&s.u[U_G2 + h * 128 + e],     pk2(wa, wa), aa);
            ab = ffma2(*(const ull*)&s.u[U_G2 + h * 128 + e + 1], pk2(wb, wb), ab);
        }
        float bv = in_b[2 * E_ + tid];
        *(ull*)&s.u[U_O2 + tid] = add2(add2(aa, ab), pk2(bv, bv));
    }
    __syncthreads();

    // out proj
    {
        ull aa = 0, ab = 0;
        #pragma unroll 8
        for (int e = 0; e < E_; e += 2) {
            float wa = g_woT[e * E_ + tid];
            float wb = g_woT[(e + 1) * E_ + tid];
            aa = ffma2(*(const ull*)&s.u[U_O2 + e],     pk2(wa, wa), aa);
            ab = ffma2(*(const ull*)&s.u[U_O2 + e + 1], pk2(wb, wb), ab);
        }
        float ob = out_b[tid];
        float r0, r1;
        unpk(add2(add2(aa, ab), pk2(ob, ob)), r0, r1);
        g_word_embeds[(v0 + 0) * E_ + tid] = (len0 > 0) ? r0 : 0.0f;
        g_word_embeds[(v0 + 1) * E_ + tid] = (len1 > 0) ? r1 : 0.0f;
    }
}

// ---------------- conv (fp16 m16n8k16 mma) + maxpool + FC: 2 news/block -----
// (R15 version — measured ~525us; UNCHANGED)
#define CONV_STEP(sv, buf)                                                        \
    do {                                                                          \
        const int j_ = (sv) >> 3, ec_ = (sv) & 7;                                 \
        const uint32_t* dp = dbase + (tb + j_ + (lane >> 2)) * DS2                \
                             + ec_ * 8 + (lane & 3);                              \
        uint32_t a0 = dp[0],            a1 = dp[8 * DS2];                         \
        uint32_t a2 = dp[4],            a3 = dp[8 * DS2 + 4];                     \
        uint32_t a4 = dp[16 * DS2],     a5 = dp[24 * DS2];                        \
        uint32_t a6 = dp[16 * DS2 + 4], a7 = dp[24 * DS2 + 4];                    \
        _Pragma("unroll")                                                         \
        for (int p = 0; p < 4; ++p) {                                             \
            uint4 bb = (buf)[p];                                                  \
            mma_f16(d[0][2 * p],     a0, a1, a2, a3, bb.x, bb.y);                 \
            mma_f16(d[1][2 * p],     a4, a5, a6, a7, bb.x, bb.y);                 \
            mma_f16(d[0][2 * p + 1], a0, a1, a2, a3, bb.z, bb.w);                 \
            mma_f16(d[1][2 * p + 1], a4, a5, a6, a7, bb.z, bb.w);                 \
        }                                                                         \
    } while (0)

template <int K>
__device__ __forceinline__ void conv_mma_phase(
    const uint4* __restrict__ B, const float* __restrict__ bias,
    const uint32_t* __restrict__ doc, float* pp, float* feats, int kidx, int tid)
{
    const int lane = tid & 31, warp = tid >> 5;
    const int news = warp >> 2;
    const int tb = ((warp >> 1) & 1) * 32;
    const int chalf = warp & 1;
    const uint32_t* dbase = doc + news * DOCN2;
    constexpr int S = K * 8;                   // even (24/32/40)

    float d[2][8][4];
    #pragma unroll
    for (int mt = 0; mt < 2; ++mt)
        #pragma unroll
        for (int nt = 0; nt < 8; ++nt)
            #pragma unroll
            for (int k = 0; k < 4; ++k) d[mt][nt][k] = 0.0f;

    const uint4* bp = B + chalf * 128 + lane;
    uint4 bufA[4], bufB[4];
    #pragma unroll
    for (int p = 0; p < 4; ++p) bufA[p] = bp[p * 32];          // step 0

    for (int s = 0; s < S; s += 2) {
        #pragma unroll
        for (int p = 0; p < 4; ++p) bufB[p] = bp[(s + 1) * 256 + p * 32];
        CONV_STEP(s, bufA);
        #pragma unroll
        for (int p = 0; p < 4; ++p) bufA[p] = bp[(s + 2) * 256 + p * 32];  // padded
        CONV_STEP(s + 1, bufB);
    }

    // max over valid t within warp, then across lane-groups
    constexpr int T = L_ - K + 1;
    #pragma unroll
    for (int nt = 0; nt < 8; ++nt)
        #pragma unroll
        for (int r = 0; r < 2; ++r) {
            float m = -1e30f;
            #pragma unroll
            for (int mt = 0; mt < 2; ++mt)
                #pragma unroll
                for (int rr = 0; rr < 2; ++rr) {
                    int tl = tb + 16 * mt + (lane >> 2) + 8 * rr;
                    if (tl < T) m = fmaxf(m, d[mt][nt][2 * rr + r]);
                }
            m = fmaxf(m, __shfl_xor_sync(0xFFFFFFFFu, m, 4));
            m = fmaxf(m, __shfl_xor_sync(0xFFFFFFFFu, m, 8));
            m = fmaxf(m, __shfl_xor_sync(0xFFFFFFFFu, m, 16));
            if (lane < 4) pp[warp * 64 + nt * 8 + 2 * lane + r] = m;
        }
    __syncthreads();
    {
        const int c = tid & 127, b = tid >> 7;
        const int ch = c >> 6, cl = c & 63;
        float v = fmaxf(pp[(b * 4 + ch) * 64 + cl],
                        pp[(b * 4 + 2 + ch) * 64 + cl]);
        feats[b * 384 + kidx * 128 + c] = fmaxf(v + bias[c], 0.0f);
    }
    __syncthreads();
}

__global__ __launch_bounds__(256, 2) void conv_mma_kernel(
    const int* __restrict__ news_words,
    const float* __restrict__ b3, const float* __restrict__ b4, const float* __restrict__ b5,
    const float* __restrict__ fcT, const float* __restrict__ fc_b,
    float* __restrict__ out)
{
    extern __shared__ uint32_t cs[];
    uint32_t* doc   = cs;                               // 2*DOCN2 u32 (half2 pairs)
    float*    pp    = (float*)(cs + 2 * DOCN2);         // 8*64
    float*    feats = pp + 512;                         // 2*384
    int*      idx2  = (int*)(feats + 768);              // 128

    const int n0 = blockIdx.x * 2;
    const int tid = threadIdx.x;

    if (tid < 128) idx2[tid] = news_words[n0 * L_ + tid];   // 2*64 indices
    __syncthreads();

    // gather doc rows as half2 pairs: g = news, pair = q&63, rowgroup = q>>6
    {
        const int g = tid >> 7, q = tid & 127;
        const int pair = q & 63, rg = q >> 6;
        #pragma unroll 4
        for (int l = 0; l < L_; l += 2) {
            int row = l + rg;
            float2 v = *reinterpret_cast<const float2*>(
                &g_word_embeds[idx2[g * L_ + row] * E_ + pair * 2]);
            __half2 h = __floats2half2_rn(v.x, v.y);
            doc[g * DOCN2 + row * DS2 + pair] = *reinterpret_cast<uint32_t*>(&h);
        }
    }
    // zero pad rows 64..67 of each news
    for (int i = tid; i < 2 * 4 * DS2; i += 256) {
        int b = i / (4 * DS2);
        int rem = i - b * (4 * DS2);
        doc[b * DOCN2 + 64 * DS2 + rem] = 0;
    }
    __syncthreads();

    conv_mma_phase<3>(g_wmma + WOFF3, b3, doc, pp, feats, 0, tid);
    conv_mma_phase<4>(g_wmma + WOFF4, b4, doc, pp, feats, 1, tid);
    conv_mma_phase<5>(g_wmma + WOFF5, b5, doc, pp, feats, 2, tid);

    // FC epilogue: out[n, i] = fc_b[i] + feats . fcT[:, i]
    {
        const int i = tid & 127, b = tid >> 7;
        float acc = fc_b[i];
        #pragma unroll 8
        for (int k = 0; k < 3 * C_; ++k) acc += feats[b * 384 + k] * fcT[k * E_ + i];
        out[(n0 + b) * E_ + i] = acc;
    }
}

// ---------------- launch ----------------
extern "C" void kernel_launch(void* const* d_in, const int* in_sizes, int n_in,
                              void* d_out, int out_size) {
    const int*   word2news     = (const int*)d_in[0];
    const int*   word2news_len = (const int*)d_in[1];
    const int*   news_words    = (const int*)d_in[2];
    const float* table         = (const float*)d_in[3];
    const float* in_w          = (const float*)d_in[4];
    const float* in_b          = (const float*)d_in[5];
    const float* out_w         = (const float*)d_in[6];
    const float* out_b         = (const float*)d_in[7];
    const float* w3            = (const float*)d_in[8];
    const float* b3            = (const float*)d_in[9];
    const float* w4            = (const float*)d_in[10];
    const float* b4            = (const float*)d_in[11];
    const float* w5            = (const float*)d_in[12];
    const float* b5            = (const float*)d_in[13];
    const float* fc_w          = (const float*)d_in[14];
    const float* fc_b          = (const float*)d_in[15];
    float* out = (float*)d_out;

    float* fcT;
    cudaGetSymbolAddress((void**)&fcT, g_fcT);

    const int word_smem = (int)sizeof(WSmem);                  // ~40.5 KB -> 5 blocks/SM
    const int conv_smem = (2 * DOCN2 + 512 + 768 + 128) * 4;   // ~42.6 KB -> 2 blocks/SM
    cudaFuncSetAttribute(word_embed_kernel,
                         cudaFuncAttributeMaxDynamicSharedMemorySize, word_smem);
    cudaFuncSetAttribute(conv_mma_kernel,
                         cudaFuncAttributeMaxDynamicSharedMemorySize, conv_smem);

    prep_t_kernel<<<(PREPT_TOTAL + 255) / 256, 256>>>(in_w, out_w);
    prep_fc_kernel<<<(PSEG3 + 255) / 256, 256>>>(fc_w);
    prep_w_kernel<<<(PREPW_TOTAL + 255) / 256, 256>>>(w3, w4, w5);

    word_embed_kernel<<<V_ / WPB, 128, word_smem>>>(
        word2news, word2news_len, table, in_b, out_b);

    conv_mma_kernel<<<N_ / 2, 256, conv_smem>>>(news_words, b3, b4, b5, fcT, fc_b, out);
}

// round 17
// speedup vs baseline: 1.1060x; 1.1060x over previous
#include <cuda_runtime.h>
#include <cuda_bf16.h>
#include <cuda_fp16.h>
#include <cstdint>

// Problem constants
#define V_  20000
#define M_  32
#define E_  128
#define H_  4
#define N_  8192
#define L_  64
#define C_  128
#define WPB 2          // words per block in word_embed kernel

// conv doc tile geometry (fp16 pairs): DS2 u32 per row (64 data + 4 pad)
#define DS2 68
#define DOCROWS 68             // 64 + 4 pad rows (pads only feed discarded t)
#define DOCN2  (DOCROWS * DS2)

// ---------------- device scratch (no allocations allowed) ----------------
__device__ float g_word_embeds[V_ * E_];          // [V,E]
__device__ float g_fcT[3 * C_ * E_];              // [i][c] = fc_w[c][i]
// duplicated-pair weight copies for FFMA2 paths: value (w,w) per element
__device__ float2 g_wq2[E_ * E_];                 // [e*128+i] = dup(Wq[i][e])
__device__ float2 g_wk2[E_ * E_];                 // [r*128+i] = dup(Wk[r][i])
__device__ float2 g_wv2[E_ * E_];                 // [e*128+i] = dup(Wv[i][e])
__device__ float2 g_wo2[E_ * E_];                 // [e*128+i] = dup(out_w[i][e])
// fragment-packed fp16 conv weights (+256 pad uint4 for unguarded prefetch)
__device__ uint4 g_wmma[24576 + 256];
#define WOFF3 0
#define WOFF4 6144     // 3*8*1024/4
#define WOFF5 14336    // 6144 + 4*8*1024/4

typedef unsigned long long ull;

// ---------------- f32x2 helpers ----------------
__device__ __forceinline__ ull pk2(float x, float y) {
    ull r;
    asm("mov.b64 %0, {%1,%2};" : "=l"(r) : "f"(x), "f"(y));
    return r;
}
__device__ __forceinline__ void unpk(ull v, float& x, float& y) {
    asm("mov.b64 {%0,%1}, %2;" : "=f"(x), "=f"(y) : "l"(v));
}
__device__ __forceinline__ ull ffma2(ull a, ull b, ull c) {
    ull d;
    asm("fma.rn.f32x2 %0, %1, %2, %3;" : "=l"(d) : "l"(a), "l"(b), "l"(c));
    return d;
}
__device__ __forceinline__ ull add2(ull a, ull b) {
    ull d;
    asm("add.rn.f32x2 %0, %1, %2;" : "=l"(d) : "l"(a), "l"(b));
    return d;
}

// fp16 m16n8k16 MMA, fp32 accumulate
__device__ __forceinline__ void mma_f16(float* d,
                                        uint32_t a0, uint32_t a1, uint32_t a2, uint32_t a3,
                                        uint32_t b0, uint32_t b1) {
    asm volatile(
        "mma.sync.aligned.m16n8k16.row.col.f32.f16.f16.f32 "
        "{%0,%1,%2,%3}, {%4,%5,%6,%7}, {%8,%9}, {%0,%1,%2,%3};"
        : "+f"(d[0]), "+f"(d[1]), "+f"(d[2]), "+f"(d[3])
        : "r"(a0), "r"(a1), "r"(a2), "r"(a3), "r"(b0), "r"(b1));
}

// ---------------- prep kernels (three launches: word lands at ncu index 3) --
#define PSEG3 (3 * C_ * E_)
#define PW3   (3 * 8 * 1024)
#define PW4   (4 * 8 * 1024)
#define PW5   (5 * 8 * 1024)
#define PREPW_TOTAL (PW3 + PW4 + PW5)
#define PREPT_TOTAL (4 * E_ * E_)

__global__ void prep_t_kernel(const float* __restrict__ in_w,
                              const float* __restrict__ out_w) {
    int idx = blockIdx.x * blockDim.x + threadIdx.x;
    if (idx >= PREPT_TOTAL) return;
    int seg = idx >> 14;          // 16384 per segment
    int r   = idx & 16383;
    int a = r >> 7, i = r & 127;
    float v;
    if (seg == 0)      { v = in_w[i * E_ + a];               g_wq2[r] = make_float2(v, v); }
    else if (seg == 1) { v = in_w[(E_ + a) * E_ + i];        g_wk2[r] = make_float2(v, v); }
    else if (seg == 2) { v = in_w[(2 * E_ + i) * E_ + a];    g_wv2[r] = make_float2(v, v); }
    else               { v = out_w[i * E_ + a];              g_wo2[r] = make_float2(v, v); }
}

__global__ void prep_fc_kernel(const float* __restrict__ fc_w) {
    int idx = blockIdx.x * blockDim.x + threadIdx.x;
    if (idx >= PSEG3) return;
    int i = idx >> 7, c = idx & 127;
    g_fcT[idx] = fc_w[c * (3 * C_) + i];
}

// fp16 k16 fragment pack (unchanged from R15)
__device__ __forceinline__ void prep_wmma_one(const float* __restrict__ w, int K,
                                              int dst_off_u4, int idx) {
    int s    = idx >> 10;
    int rem  = idx & 1023;
    int p    = rem >> 7;
    int lane = (rem >> 2) & 31;
    int q    = rem & 3;
    int j   = s >> 3, ec8 = s & 7;
    int nt  = 2 * p + (q >> 1);
    int klo = 2 * (lane & 3) + 8 * (q & 1);
    int c   = nt * 8 + (lane >> 2);
    int e   = ec8 * 16 + klo;
    __half2 h = __floats2half2_rn(w[(c * E_ + e) * K + j],
                                  w[(c * E_ + e + 1) * K + j]);
    reinterpret_cast<uint32_t*>(g_wmma)[dst_off_u4 * 4 + idx] =
        *reinterpret_cast<uint32_t*>(&h);
}

__global__ void prep_w_kernel(const float* __restrict__ w3,
                              const float* __restrict__ w4,
                              const float* __restrict__ w5) {
    int idx = blockIdx.x * blockDim.x + threadIdx.x;
    if (idx >= PREPW_TOTAL) return;
    if (idx < PW3) { prep_wmma_one(w3, 3, WOFF3, idx); return; }
    idx -= PW3;
    if (idx < PW4) { prep_wmma_one(w4, 4, WOFF4, idx); return; }
    idx -= PW4;
    prep_wmma_one(w5, 5, WOFF5, idx);
}

// ---------------- word embedding kernel: 2 words per block, f32x2-packed ----
// R15 weight scheme (LDG.64 dup weights) + FULLY UNROLLED weight GEMV loops so
// ptxas batches loads deep (MLP up); launch_bounds(128,5) caps regs at the
// 5-CTA budget (occupancy is smem-pinned at 5 anyway).
struct WSmem {
    float2 ctx2[M_][129];
    float2 u[900];
    int idx[WPB][M_];
    int len[WPB];
};
#define U_Q2   0
#define U_QH2  128
#define U_G2   256
#define U_ATT  768
#define U_O2   0
#define U_CB   896

__global__ __launch_bounds__(128, 5) void word_embed_kernel(
    const int* __restrict__ word2news, const int* __restrict__ word2news_len,
    const float* __restrict__ table,
    const float* __restrict__ in_b, const float* __restrict__ out_b)
{
    extern __shared__ char smem_raw[];
    WSmem& s = *reinterpret_cast<WSmem*>(smem_raw);

    const int v0 = blockIdx.x * WPB;
    const int tid = threadIdx.x;
    const int lane = tid & 31, warp = tid >> 5;

    if (tid < WPB * M_) {
        int w = tid >> 5, m = tid & 31;
        s.idx[w][m] = word2news[(v0 + w) * M_ + m];
    }
    if (tid < WPB) s.len[tid] = word2news_len[v0 + tid];
    __syncthreads();

    const int len0 = s.len[0], len1 = s.len[1];

    // gather ctx rows: warp handles row m = m4*4 + warp, loads BOTH words
    #pragma unroll
    for (int m4 = 0; m4 < 8; ++m4) {
        int m = m4 * 4 + warp;
        float4 a = *reinterpret_cast<const float4*>(&table[s.idx[0][m] * E_ + lane * 4]);
        float4 b = *reinterpret_cast<const float4*>(&table[s.idx[1][m] * E_ + lane * 4]);
        s.ctx2[m][lane * 4 + 0] = make_float2(a.x, b.x);
        s.ctx2[m][lane * 4 + 1] = make_float2(a.y, b.y);
        s.ctx2[m][lane * 4 + 2] = make_float2(a.z, b.z);
        s.ctx2[m][lane * 4 + 3] = make_float2(a.w, b.w);
    }
    __syncthreads();

    // masked mean query (scalar masks differ per word)
    {
        float inv0 = 1.0f / (float)(len0 > 0 ? len0 : 1);
        float inv1 = 1.0f / (float)(len1 > 0 ? len1 : 1);
        float a0 = 0.0f, a1 = 0.0f;
        #pragma unroll
        for (int m = 0; m < M_; ++m) {
            float2 v = s.ctx2[m][tid];
            if (m < len0) a0 += v.x;
            if (m < len1) a1 += v.y;
        }
        s.u[U_Q2 + tid] = make_float2(a0 * inv0, a1 * inv1);
    }
    __syncthreads();

    // qh = q @ Wq^T + bq       (FFMA2, LDG.64 dup weights, full unroll -> deep MLP)
    {
        const ull* wq2 = (const ull*)g_wq2;
        ull aa = 0, ab = 0;
        #pragma unroll
        for (int e = 0; e < E_; e += 2) {
            aa = ffma2(*(const ull*)&s.u[U_Q2 + e],     wq2[e * E_ + tid],       aa);
            ab = ffma2(*(const ull*)&s.u[U_Q2 + e + 1], wq2[(e + 1) * E_ + tid], ab);
        }
        float bq = in_b[tid];
        *(ull*)&s.u[U_QH2 + tid] = add2(add2(aa, ab), pk2(bq, bq));
    }
    __syncthreads();

    // g2[h][e] = sum_d qh[h*32+d] * Wk[h*32+d][e]   (full unroll per head)
    {
        const ull* wk2 = (const ull*)g_wk2;
        #pragma unroll
        for (int h = 0; h < H_; ++h) {
            ull aa = 0, ab = 0;
            #pragma unroll
            for (int d = 0; d < 32; d += 2) {
                aa = ffma2(*(const ull*)&s.u[U_QH2 + h * 32 + d],
                           wk2[(h * 32 + d) * E_ + tid], aa);
                ab = ffma2(*(const ull*)&s.u[U_QH2 + h * 32 + d + 1],
                           wk2[(h * 32 + d + 1) * E_ + tid], ab);
            }
            *(ull*)&s.u[U_G2 + h * 128 + tid] = add2(aa, ab);
        }
    }
    if (tid < WPB * H_) {
        int w = tid >> 2, h = tid & 3;
        float c = 0.0f;
        #pragma unroll 8
        for (int d = 0; d < 32; ++d) {
            float2 q2v = s.u[U_QH2 + h * 32 + d];
            c += (w == 0 ? q2v.x : q2v.y) * in_b[E_ + h * 32 + d];
        }
        ((float*)(s.u + U_CB))[h * 2 + w] = c;
    }
    __syncthreads();

    // scores + per-head softmax: thread = (h = warp, m = lane); both words packed
    {
        const int h = warp, m = lane;
        ull sa = 0, sb = 0;
        #pragma unroll 8
        for (int e = 0; e < E_; e += 2) {
            sa = ffma2(*(const ull*)&s.ctx2[m][e],
                       *(const ull*)&s.u[U_G2 + h * 128 + e], sa);
            sb = ffma2(*(const ull*)&s.ctx2[m][e + 1],
                       *(const ull*)&s.u[U_G2 + h * 128 + e + 1], sb);
        }
        float s0, s1;
        unpk(add2(sa, sb), s0, s1);
        float2 cb = s.u[U_CB + h];
        s0 = (s0 + cb.x) * 0.17677669529663688f;
        s1 = (s1 + cb.y) * 0.17677669529663688f;
        if (m >= len0) s0 = -1e30f;
        if (m >= len1) s1 = -1e30f;
        float w0 = s0, w1 = s1;
        #pragma unroll
        for (int o = 16; o; o >>= 1) {
            w0 = fmaxf(w0, __shfl_xor_sync(0xFFFFFFFFu, w0, o));
            w1 = fmaxf(w1, __shfl_xor_sync(0xFFFFFFFFu, w1, o));
        }
        float p0 = __expf(s0 - w0), p1 = __expf(s1 - w1);
        float ps0 = p0, ps1 = p1;
        #pragma unroll
        for (int o = 16; o; o >>= 1) {
            ps0 += __shfl_xor_sync(0xFFFFFFFFu, ps0, o);
            ps1 += __shfl_xor_sync(0xFFFFFFFFu, ps1, o);
        }
        *(ull*)&s.u[U_ATT + h * 32 + m] = pk2(p0 / ps0, p1 / ps1);
    }
    __syncthreads();

    // ch2[h][e] = sum_m attn[h,m] * ctx[m,e]   (overwrites g2 region)
    {
        #pragma unroll
        for (int h = 0; h < H_; ++h) {
            ull aa = 0, ab = 0;
            #pragma unroll 8
            for (int m = 0; m < M_; m += 2) {
                aa = ffma2(*(const ull*)&s.u[U_ATT + h * 32 + m],
                           *(const ull*)&s.ctx2[m][tid], aa);
                ab = ffma2(*(const ull*)&s.u[U_ATT + h * 32 + m + 1],
                           *(const ull*)&s.ctx2[m + 1][tid], ab);
            }
            *(ull*)&s.u[U_G2 + h * 128 + tid] = add2(aa, ab);
        }
    }
    __syncthreads();

    // o[i] = ch[h(i)] . Wv[i] + bv[i]    (o2 aliases q2; full unroll)
    {
        const int h = warp;
        const ull* wv2 = (const ull*)g_wv2;
        ull aa = 0, ab = 0;
        #pragma unroll
        for (int e = 0; e < E_; e += 2) {
            aa = ffma2(*(const ull*)&s.u[U_G2 + h * 128 + e],     wv2[e * E_ + tid],       aa);
            ab = ffma2(*(const ull*)&s.u[U_G2 + h * 128 + e + 1], wv2[(e + 1) * E_ + tid], ab);
        }
        float bv = in_b[2 * E_ + tid];
        *(ull*)&s.u[U_O2 + tid] = add2(add2(aa, ab), pk2(bv, bv));
    }
    __syncthreads();

    // out proj (full unroll)
    {
        const ull* wo2 = (const ull*)g_wo2;
        ull aa = 0, ab = 0;
        #pragma unroll
        for (int e = 0; e < E_; e += 2) {
            aa = ffma2(*(const ull*)&s.u[U_O2 + e],     wo2[e * E_ + tid],       aa);
            ab = ffma2(*(const ull*)&s.u[U_O2 + e + 1], wo2[(e + 1) * E_ + tid], ab);
        }
        float ob = out_b[tid];
        float r0, r1;
        unpk(add2(add2(aa, ab), pk2(ob, ob)), r0, r1);
        g_word_embeds[(v0 + 0) * E_ + tid] = (len0 > 0) ? r0 : 0.0f;
        g_word_embeds[(v0 + 1) * E_ + tid] = (len1 > 0) ? r1 : 0.0f;
    }
}

// ---------------- conv (fp16 m16n8k16 mma) + maxpool + FC: 2 news/block -----
// (R15 version — measured ~525us; UNCHANGED)
#define CONV_STEP(sv, buf)                                                        \
    do {                                                                          \
        const int j_ = (sv) >> 3, ec_ = (sv) & 7;                                 \
        const uint32_t* dp = dbase + (tb + j_ + (lane >> 2)) * DS2                \
                             + ec_ * 8 + (lane & 3);                              \
        uint32_t a0 = dp[0],            a1 = dp[8 * DS2];                         \
        uint32_t a2 = dp[4],            a3 = dp[8 * DS2 + 4];                     \
        uint32_t a4 = dp[16 * DS2],     a5 = dp[24 * DS2];                        \
        uint32_t a6 = dp[16 * DS2 + 4], a7 = dp[24 * DS2 + 4];                    \
        _Pragma("unroll")                                                         \
        for (int p = 0; p < 4; ++p) {                                             \
            uint4 bb = (buf)[p];                                                  \
            mma_f16(d[0][2 * p],     a0, a1, a2, a3, bb.x, bb.y);                 \
            mma_f16(d[1][2 * p],     a4, a5, a6, a7, bb.x, bb.y);                 \
            mma_f16(d[0][2 * p + 1], a0, a1, a2, a3, bb.z, bb.w);                 \
            mma_f16(d[1][2 * p + 1], a4, a5, a6, a7, bb.z, bb.w);                 \
        }                                                                         \
    } while (0)

template <int K>
__device__ __forceinline__ void conv_mma_phase(
    const uint4* __restrict__ B, const float* __restrict__ bias,
    const uint32_t* __restrict__ doc, float* pp, float* feats, int kidx, int tid)
{
    const int lane = tid & 31, warp = tid >> 5;
    const int news = warp >> 2;
    const int tb = ((warp >> 1) & 1) * 32;
    const int chalf = warp & 1;
    const uint32_t* dbase = doc + news * DOCN2;
    constexpr int S = K * 8;                   // even (24/32/40)

    float d[2][8][4];
    #pragma unroll
    for (int mt = 0; mt < 2; ++mt)
        #pragma unroll
        for (int nt = 0; nt < 8; ++nt)
            #pragma unroll
            for (int k = 0; k < 4; ++k) d[mt][nt][k] = 0.0f;

    const uint4* bp = B + chalf * 128 + lane;
    uint4 bufA[4], bufB[4];
    #pragma unroll
    for (int p = 0; p < 4; ++p) bufA[p] = bp[p * 32];          // step 0

    for (int s = 0; s < S; s += 2) {
        #pragma unroll
        for (int p = 0; p < 4; ++p) bufB[p] = bp[(s + 1) * 256 + p * 32];
        CONV_STEP(s, bufA);
        #pragma unroll
        for (int p = 0; p < 4; ++p) bufA[p] = bp[(s + 2) * 256 + p * 32];  // padded
        CONV_STEP(s + 1, bufB);
    }

    // max over valid t within warp, then across lane-groups
    constexpr int T = L_ - K + 1;
    #pragma unroll
    for (int nt = 0; nt < 8; ++nt)
        #pragma unroll
        for (int r = 0; r < 2; ++r) {
            float m = -1e30f;
            #pragma unroll
            for (int mt = 0; mt < 2; ++mt)
                #pragma unroll
                for (int rr = 0; rr < 2; ++rr) {
                    int tl = tb + 16 * mt + (lane >> 2) + 8 * rr;
                    if (tl < T) m = fmaxf(m, d[mt][nt][2 * rr + r]);
                }
            m = fmaxf(m, __shfl_xor_sync(0xFFFFFFFFu, m, 4));
            m = fmaxf(m, __shfl_xor_sync(0xFFFFFFFFu, m, 8));
            m = fmaxf(m, __shfl_xor_sync(0xFFFFFFFFu, m, 16));
            if (lane < 4) pp[warp * 64 + nt * 8 + 2 * lane + r] = m;
        }
    __syncthreads();
    {
        const int c = tid & 127, b = tid >> 7;
        const int ch = c >> 6, cl = c & 63;
        float v = fmaxf(pp[(b * 4 + ch) * 64 + cl],
                        pp[(b * 4 + 2 + ch) * 64 + cl]);
        feats[b * 384 + kidx * 128 + c] = fmaxf(v + bias[c], 0.0f);
    }
    __syncthreads();
}

__global__ __launch_bounds__(256, 2) void conv_mma_kernel(
    const int* __restrict__ news_words,
    const float* __restrict__ b3, const float* __restrict__ b4, const float* __restrict__ b5,
    const float* __restrict__ fcT, const float* __restrict__ fc_b,
    float* __restrict__ out)
{
    extern __shared__ uint32_t cs[];
    uint32_t* doc   = cs;                               // 2*DOCN2 u32 (half2 pairs)
    float*    pp    = (float*)(cs + 2 * DOCN2);         // 8*64
    float*    feats = pp + 512;                         // 2*384
    int*      idx2  = (int*)(feats + 768);              // 128

    const int n0 = blockIdx.x * 2;
    const int tid = threadIdx.x;

    if (tid < 128) idx2[tid] = news_words[n0 * L_ + tid];   // 2*64 indices
    __syncthreads();

    // gather doc rows as half2 pairs: g = news, pair = q&63, rowgroup = q>>6
    {
        const int g = tid >> 7, q = tid & 127;
        const int pair = q & 63, rg = q >> 6;
        #pragma unroll 4
        for (int l = 0; l < L_; l += 2) {
            int row = l + rg;
            float2 v = *reinterpret_cast<const float2*>(
                &g_word_embeds[idx2[g * L_ + row] * E_ + pair * 2]);
            __half2 h = __floats2half2_rn(v.x, v.y);
            doc[g * DOCN2 + row * DS2 + pair] = *reinterpret_cast<uint32_t*>(&h);
        }
    }
    // zero pad rows 64..67 of each news
    for (int i = tid; i < 2 * 4 * DS2; i += 256) {
        int b = i / (4 * DS2);
        int rem = i - b * (4 * DS2);
        doc[b * DOCN2 + 64 * DS2 + rem] = 0;
    }
    __syncthreads();

    conv_mma_phase<3>(g_wmma + WOFF3, b3, doc, pp, feats, 0, tid);
    conv_mma_phase<4>(g_wmma + WOFF4, b4, doc, pp, feats, 1, tid);
    conv_mma_phase<5>(g_wmma + WOFF5, b5, doc, pp, feats, 2, tid);

    // FC epilogue: out[n, i] = fc_b[i] + feats . fcT[:, i]
    {
        const int i = tid & 127, b = tid >> 7;
        float acc = fc_b[i];
        #pragma unroll 8
        for (int k = 0; k < 3 * C_; ++k) acc += feats[b * 384 + k] * fcT[k * E_ + i];
        out[(n0 + b) * E_ + i] = acc;
    }
}

// ---------------- launch ----------------
extern "C" void kernel_launch(void* const* d_in, const int* in_sizes, int n_in,
                              void* d_out, int out_size) {
    const int*   word2news     = (const int*)d_in[0];
    const int*   word2news_len = (const int*)d_in[1];
    const int*   news_words    = (const int*)d_in[2];
    const float* table         = (const float*)d_in[3];
    const float* in_w          = (const float*)d_in[4];
    const float* in_b          = (const float*)d_in[5];
    const float* out_w         = (const float*)d_in[6];
    const float* out_b         = (const float*)d_in[7];
    const float* w3            = (const float*)d_in[8];
    const float* b3            = (const float*)d_in[9];
    const float* w4            = (const float*)d_in[10];
    const float* b4            = (const float*)d_in[11];
    const float* w5            = (const float*)d_in[12];
    const float* b5            = (const float*)d_in[13];
    const float* fc_w          = (const float*)d_in[14];
    const float* fc_b          = (const float*)d_in[15];
    float* out = (float*)d_out;

    float* fcT;
    cudaGetSymbolAddress((void**)&fcT, g_fcT);

    const int word_smem = (int)sizeof(WSmem);                  // ~40.5 KB -> 5 blocks/SM
    const int conv_smem = (2 * DOCN2 + 512 + 768 + 128) * 4;   // ~42.6 KB -> 2 blocks/SM
    cudaFuncSetAttribute(word_embed_kernel,
                         cudaFuncAttributeMaxDynamicSharedMemorySize, word_smem);
    cudaFuncSetAttribute(conv_mma_kernel,
                         cudaFuncAttributeMaxDynamicSharedMemorySize, conv_smem);

    prep_t_kernel<<<(PREPT_TOTAL + 255) / 256, 256>>>(in_w, out_w);
    prep_fc_kernel<<<(PSEG3 + 255) / 256, 256>>>(fc_w);
    prep_w_kernel<<<(PREPW_TOTAL + 255) / 256, 256>>>(w3, w4, w5);

    word_embed_kernel<<<V_ / WPB, 128, word_smem>>>(
        word2news, word2news_len, table, in_b, out_b);

    conv_mma_kernel<<<N_ / 2, 256, conv_smem>>>(news_words, b3, b4, b5, fcT, fc_b, out);
}